// round 4
// baseline (speedup 1.0000x reference)
#include <cuda_runtime.h>
#include <cuda_bf16.h>
#include <math.h>

// LRML memory-network scoring — smem-transpose, thread-per-element compute.
//  0: user_ids  int32  [B]
//  1: item_ids  int32  [B]
//  2: user_emb  f32    [U, 32]
//  3: item_emb  f32    [I, 32]
//  4: W_att     f32    [10, 32]
//  5: memory    f32    [10, 32]
// Output: f32 [B] = -sum((ue + rel - ie)^2)
//
// Phase 1: coalesced gather of 128 rows (64 user + 64 item) into shared
//          memory, 8 lanes per row, row stride 144B (== 16 mod 128) so
//          phase-2 per-thread float4 reads are bank-conflict-free.
// Phase 2: thread t computes element t start-to-finish: zero shuffles,
//          softmax once per element, everything register-resident.

#define M 10
#define EPB 64                 // elements per block == threads per block
#define ROW_STRIDE 36          // floats per row slot (144 bytes)

__global__ __launch_bounds__(EPB)
void LRML_90804198572513_kernel(const int* __restrict__ user_ids,
                                const int* __restrict__ item_ids,
                                const float* __restrict__ user_emb,
                                const float* __restrict__ item_emb,
                                const float* __restrict__ W_att,
                                const float* __restrict__ memory,
                                float* __restrict__ out,
                                int B) {
    __shared__ __align__(16) float rows[2 * EPB * ROW_STRIDE]; // u rows then i rows
    __shared__ __align__(16) float4 sW[M * 8];                 // W_att
    __shared__ __align__(16) float4 sM[M * 8];                 // memory
    __shared__ int sids[2 * EPB];

    const int tid  = threadIdx.x;
    const int base = blockIdx.x * EPB;
    const int b    = base + tid;

    // --- Stage ids and the tiny parameter matrices ---
    sids[tid]       = user_ids[b];
    sids[EPB + tid] = item_ids[b];
    for (int i = tid; i < M * 8; i += EPB) {
        sW[i] = ((const float4*)W_att)[i];
        sM[i] = ((const float4*)memory)[i];
    }
    __syncthreads();

    // --- Phase 1: coalesced row gather ---
    // 128 rows x 8 float4 = 1024 float4, 16 per thread. Consecutive lanes
    // cover consecutive float4s, so 8-lane groups read full 128B rows.
    #pragma unroll
    for (int c = 0; c < 16; c++) {
        const int g   = c * EPB + tid;
        const int row = g >> 3;          // 0..127
        const int sub = g & 7;           // float4 index within row
        const float* tab = (row < EPB) ? user_emb : item_emb;
        const size_t id = (size_t)sids[row];
        const float4 v = ((const float4*)(tab + id * 32))[sub];
        *(float4*)&rows[row * ROW_STRIDE + sub * 4] = v;
    }
    __syncthreads();

    // --- Phase 2: thread t owns element t ---
    const float* urow = &rows[tid * ROW_STRIDE];
    const float* irow = &rows[(EPB + tid) * ROW_STRIDE];

    // Load both rows into registers; accumulate norms and unscaled scores.
    float4 u[8], iv[8];
    float nu = 0.0f, ni = 0.0f;
    float s[M];
    #pragma unroll
    for (int m = 0; m < M; m++) s[m] = 0.0f;

    #pragma unroll
    for (int k = 0; k < 8; k++) {
        u[k]  = *(const float4*)&urow[k * 4];
        iv[k] = *(const float4*)&irow[k * 4];
        nu = fmaf(u[k].x, u[k].x, nu);  nu = fmaf(u[k].y, u[k].y, nu);
        nu = fmaf(u[k].z, u[k].z, nu);  nu = fmaf(u[k].w, u[k].w, nu);
        ni = fmaf(iv[k].x, iv[k].x, ni); ni = fmaf(iv[k].y, iv[k].y, ni);
        ni = fmaf(iv[k].z, iv[k].z, ni); ni = fmaf(iv[k].w, iv[k].w, ni);
        // unscaled joint chunk
        float4 j;
        j.x = u[k].x * iv[k].x; j.y = u[k].y * iv[k].y;
        j.z = u[k].z * iv[k].z; j.w = u[k].w * iv[k].w;
        #pragma unroll
        for (int m = 0; m < M; m++) {
            const float4 w = sW[m * 8 + k];   // broadcast LDS
            s[m] = fmaf(j.x, w.x, s[m]); s[m] = fmaf(j.y, w.y, s[m]);
            s[m] = fmaf(j.z, w.z, s[m]); s[m] = fmaf(j.w, w.w, s[m]);
        }
    }

    // scale = 1/max(||e||,1) = min(rsqrt(n),1)  (n=0 -> inf -> 1, fine)
    const float su = fminf(rsqrtf(nu), 1.0f);
    const float si = fminf(rsqrtf(ni), 1.0f);
    const float sj = su * si;

    // Softmax over M=10 (once per element).
    float mx = s[0] * sj;
    #pragma unroll
    for (int m = 0; m < M; m++) { s[m] *= sj; mx = fmaxf(mx, s[m]); }
    float sum = 0.0f;
    #pragma unroll
    for (int m = 0; m < M; m++) { s[m] = __expf(s[m] - mx); sum += s[m]; }
    const float inv = 1.0f / sum;
    #pragma unroll
    for (int m = 0; m < M; m++) s[m] *= inv;   // p[m]

    // rel chunk-by-chunk, immediately consumed into the distance.
    float d = 0.0f;
    #pragma unroll
    for (int k = 0; k < 8; k++) {
        float4 r = make_float4(0.f, 0.f, 0.f, 0.f);
        #pragma unroll
        for (int m = 0; m < M; m++) {
            const float4 mm = sM[m * 8 + k];  // broadcast LDS
            r.x = fmaf(s[m], mm.x, r.x); r.y = fmaf(s[m], mm.y, r.y);
            r.z = fmaf(s[m], mm.z, r.z); r.w = fmaf(s[m], mm.w, r.w);
        }
        float dx;
        dx = fmaf(su, u[k].x, r.x) - si * iv[k].x; d = fmaf(dx, dx, d);
        dx = fmaf(su, u[k].y, r.y) - si * iv[k].y; d = fmaf(dx, dx, d);
        dx = fmaf(su, u[k].z, r.z) - si * iv[k].z; d = fmaf(dx, dx, d);
        dx = fmaf(su, u[k].w, r.w) - si * iv[k].w; d = fmaf(dx, dx, d);
    }

    out[b] = -d;
}

extern "C" void kernel_launch(void* const* d_in, const int* in_sizes, int n_in,
                              void* d_out, int out_size) {
    const int*   user_ids = (const int*)  d_in[0];
    const int*   item_ids = (const int*)  d_in[1];
    const float* user_emb = (const float*)d_in[2];
    const float* item_emb = (const float*)d_in[3];
    const float* W_att    = (const float*)d_in[4];
    const float* memory   = (const float*)d_in[5];
    float* out = (float*)d_out;

    const int B = in_sizes[0];
    const int grid = (B + EPB - 1) / EPB;   // B=16384 -> 256 blocks
    LRML_90804198572513_kernel<<<grid, EPB>>>(
        user_ids, item_ids, user_emb, item_emb, W_att, memory, out, B);
}